// round 12
// baseline (speedup 1.0000x reference)
#include <cuda_runtime.h>
#include <cuda_fp16.h>
#include <mma.h>

using namespace nvcuda;

#define NN 100000
#define NE 3200000
#define HID 128
#define NG  512
#define NSCB 98   // scan blocks: 98*1024 >= NN

// ---------------- static device scratch ----------------
__device__ __half g_bufA_h[NN * HID];       // post-GEMM features (fp16, gather source)
__device__ float  g_bufB[NN * HID];         // post-aggregation features (fp32)
__device__ int    g_cnt[NN];                // in-degree incl. self loop
__device__ int    g_colptr[NN + 1];         // CSR offsets (by target node)
__device__ int    g_cursor[NN];             // fill cursors
__device__ float  g_dis[NN];                // deg^{-1/2}
__device__ uint2  g_edge[NE + NN];          // packed CSR: (src, norm-bits)
__device__ int    g_part[NSCB];             // scan partials
__device__ int    g_gcnt[NG];               // nodes per graph
__device__ int    g_gptr[NG + 1];           // graph offsets (batch sorted)
__device__ float  g_pool[NG * HID];         // pooled means

// ---------------- preprocessing ----------------
__global__ void init_kernel() {
    int i = blockIdx.x * blockDim.x + threadIdx.x;
    if (i < NN) g_cnt[i] = 1;   // self-loop
    if (i < NG) g_gcnt[i] = 0;
}

// edge_index / batch are int32 (JAX x64-disabled downcasts jnp.int64)
__global__ void count_edges_kernel(const int* __restrict__ ei) {
    int e4 = blockIdx.x * blockDim.x + threadIdx.x;   // NE/4 threads
    if (e4 < NE / 4) {
        int4 c = ((const int4*)(ei + NE))[e4];
        atomicAdd(&g_cnt[c.x], 1);
        atomicAdd(&g_cnt[c.y], 1);
        atomicAdd(&g_cnt[c.z], 1);
        atomicAdd(&g_cnt[c.w], 1);
    }
}

// --- 3-phase exclusive scan of g_cnt -> g_colptr ---
__global__ void scan_blocksum_kernel() {   // 98 blocks x 1024
    __shared__ int wsum[32];
    int t = threadIdx.x, lane = t & 31, wid = t >> 5;
    int i = blockIdx.x * 1024 + t;
    int v = (i < NN) ? g_cnt[i] : 0;
    for (int off = 16; off > 0; off >>= 1) v += __shfl_down_sync(0xffffffffu, v, off);
    if (lane == 0) wsum[wid] = v;
    __syncthreads();
    if (wid == 0) {
        int s = wsum[lane];
        for (int off = 16; off > 0; off >>= 1) s += __shfl_down_sync(0xffffffffu, s, off);
        if (lane == 0) g_part[blockIdx.x] = s;
    }
}

__global__ void scan_part_kernel() {       // 1 block x 128
    __shared__ int s[128];
    int t = threadIdx.x;
    int orig = (t < NSCB) ? g_part[t] : 0;
    s[t] = orig;
    __syncthreads();
    for (int off = 1; off < 128; off <<= 1) {
        int v = (t >= off) ? s[t - off] : 0;
        __syncthreads();
        s[t] += v;
        __syncthreads();
    }
    if (t < NSCB) g_part[t] = s[t] - orig;   // exclusive
    if (t == 127) g_colptr[NN] = s[127];     // total
}

// local scan + write colptr, and fused dis/cursor production
__global__ void scan_local_kernel() {      // 98 blocks x 1024
    __shared__ int wsum[32];
    int t = threadIdx.x, lane = t & 31, wid = t >> 5;
    int i = blockIdx.x * 1024 + t;
    int v = (i < NN) ? g_cnt[i] : 0;
    int x = v;
    for (int off = 1; off < 32; off <<= 1) {
        int y = __shfl_up_sync(0xffffffffu, x, off);
        if (lane >= off) x += y;
    }
    if (lane == 31) wsum[wid] = x;
    __syncthreads();
    if (wid == 0) {
        int y = wsum[lane];
        for (int off = 1; off < 32; off <<= 1) {
            int z = __shfl_up_sync(0xffffffffu, y, off);
            if (lane >= off) y += z;
        }
        wsum[lane] = y;   // inclusive warp sums
    }
    __syncthreads();
    int woff = (wid > 0) ? wsum[wid - 1] : 0;
    if (i < NN) {
        int cp = g_part[blockIdx.x] + woff + x - v;   // exclusive
        g_colptr[i] = cp;
        g_cursor[i] = cp;
        g_dis[i]    = rsqrtf((float)v);               // v >= 1 always
    }
}

__global__ void fill_csr_kernel(const int* __restrict__ ei) {
    int idx = blockIdx.x * blockDim.x + threadIdx.x;
    if (idx < NE) {
        int r = ei[idx];
        int c = ei[NE + idx];
        int p = atomicAdd(&g_cursor[c], 1);
        g_edge[p] = make_uint2((unsigned)r, __float_as_uint(g_dis[r] * g_dis[c]));
    } else if (idx < NE + NN) {
        int i = idx - NE;           // self loop
        int p = atomicAdd(&g_cursor[i], 1);
        float d = g_dis[i];
        g_edge[p] = make_uint2((unsigned)i, __float_as_uint(d * d));
    }
}

// ---------------- GEMM (HMMA, split-W): Yh = half( X @ (Whi+Wlo) ) ----------------
// W split into fp16 hi+lo kills the systematic W-quantization error; X-side fp16
// rounding is random across nodes and averages out in pooling.
#define LDH 136                            // fp16 smem leading dim
#define SMEM_GEMM (3 * 128 * LDH * 2)      // Xs + Whi + Wlo = 104448 B; C overlaps

__global__ void __launch_bounds__(256) gemm_kernel(
    const float* __restrict__ X, const float* __restrict__ W,
    __half* __restrict__ Yh, int n)
{
    extern __shared__ char sm[];
    __half* Xs  = (__half*)sm;                 // [128][LDH]
    __half* Whi = (__half*)sm + 128 * LDH;     // [128][LDH]
    __half* Wlo = (__half*)sm + 2 * 128 * LDH; // [128][LDH]
    float*  Cs  = (float*)sm;                  // [128][128], reused after compute
    int tid = threadIdx.x;
    int warp = tid >> 5, lane = tid & 31;
    int row0 = blockIdx.x * 128;

    // load + convert: 128 rows x 16 chunks (8 halfs each)
    for (int idx = tid; idx < 128 * 16; idx += 256) {
        int r = idx >> 4, c8 = idx & 15;
        // W chunk -> hi/lo split
        float4 wa = ((const float4*)W)[r * 32 + c8 * 2];
        float4 wb = ((const float4*)W)[r * 32 + c8 * 2 + 1];
        float wf[8] = {wa.x, wa.y, wa.z, wa.w, wb.x, wb.y, wb.z, wb.w};
        __half hh[8], hl[8];
        #pragma unroll
        for (int q = 0; q < 8; q++) {
            __half h = __float2half_rn(wf[q]);
            hh[q] = h;
            hl[q] = __float2half_rn(wf[q] - __half2float(h));
        }
        *(uint4*)&Whi[r * LDH + c8 * 8] = *(uint4*)hh;
        *(uint4*)&Wlo[r * LDH + c8 * 8] = *(uint4*)hl;
        // X chunk (zero-pad past n)
        float4 xa = make_float4(0.f, 0.f, 0.f, 0.f), xb = xa;
        if (row0 + r < n) {
            xa = ((const float4*)X)[(row0 + r) * 32 + c8 * 2];
            xb = ((const float4*)X)[(row0 + r) * 32 + c8 * 2 + 1];
        }
        __half2 x0 = __floats2half2_rn(xa.x, xa.y), x1 = __floats2half2_rn(xa.z, xa.w);
        __half2 x2 = __floats2half2_rn(xb.x, xb.y), x3 = __floats2half2_rn(xb.z, xb.w);
        uint4 xp;
        xp.x = *(unsigned*)&x0; xp.y = *(unsigned*)&x1;
        xp.z = *(unsigned*)&x2; xp.w = *(unsigned*)&x3;
        *(uint4*)&Xs[r * LDH + c8 * 8] = xp;
    }
    __syncthreads();

    // each warp: 16 rows x 128 cols; acc = X@Whi + X@Wlo (fp32 accum)
    wmma::fragment<wmma::accumulator, 16, 16, 16, float> acc[8];
    #pragma unroll
    for (int j = 0; j < 8; j++) wmma::fill_fragment(acc[j], 0.f);

    #pragma unroll
    for (int k = 0; k < 8; k++) {
        wmma::fragment<wmma::matrix_a, 16, 16, 16, __half, wmma::row_major> a;
        wmma::load_matrix_sync(a, &Xs[(warp * 16) * LDH + k * 16], LDH);
        #pragma unroll
        for (int j = 0; j < 8; j++) {
            wmma::fragment<wmma::matrix_b, 16, 16, 16, __half, wmma::row_major> bh, bl;
            wmma::load_matrix_sync(bh, &Whi[(k * 16) * LDH + j * 16], LDH);
            wmma::load_matrix_sync(bl, &Wlo[(k * 16) * LDH + j * 16], LDH);
            wmma::mma_sync(acc[j], a, bh, acc[j]);
            wmma::mma_sync(acc[j], a, bl, acc[j]);
        }
    }

    __syncthreads();   // all mma smem reads done before overwriting with C
    #pragma unroll
    for (int j = 0; j < 8; j++)
        wmma::store_matrix_sync(&Cs[(warp * 16) * 128 + j * 16], acc[j], 128, wmma::mem_row_major);
    __syncwarp();

    // pack this warp's 16 rows to fp16 global (2 lanes per row, 8 chunks each)
    int r = warp * 16 + (lane >> 1);
    int gr = row0 + r;
    if (gr < n) {
        int cbase = (lane & 1) * 8;
        #pragma unroll
        for (int j = 0; j < 8; j++) {
            int c8 = cbase + j;
            float4 ca = *(float4*)&Cs[r * 128 + c8 * 8];
            float4 cb = *(float4*)&Cs[r * 128 + c8 * 8 + 4];
            __half2 p0 = __floats2half2_rn(ca.x, ca.y), p1 = __floats2half2_rn(ca.z, ca.w);
            __half2 p2 = __floats2half2_rn(cb.x, cb.y), p3 = __floats2half2_rn(cb.z, cb.w);
            uint4 o;
            o.x = *(unsigned*)&p0; o.y = *(unsigned*)&p1;
            o.z = *(unsigned*)&p2; o.w = *(unsigned*)&p3;
            ((uint4*)Yh)[gr * 16 + c8] = o;
        }
    }
}

// ---------------- aggregation: bufB[v] = relu(bias + sum_e nrm * Hh[src_e]) ----------------
__device__ __forceinline__ void agg_fma(float2* acc, uint4 v, float nrm) {
    __half2 h0 = *(__half2*)&v.x, h1 = *(__half2*)&v.y;
    __half2 h2 = *(__half2*)&v.z, h3 = *(__half2*)&v.w;
    float2 f0 = __half22float2(h0), f1 = __half22float2(h1);
    float2 f2 = __half22float2(h2), f3 = __half22float2(h3);
    acc[0].x = fmaf(nrm, f0.x, acc[0].x); acc[0].y = fmaf(nrm, f0.y, acc[0].y);
    acc[1].x = fmaf(nrm, f1.x, acc[1].x); acc[1].y = fmaf(nrm, f1.y, acc[1].y);
    acc[2].x = fmaf(nrm, f2.x, acc[2].x); acc[2].y = fmaf(nrm, f2.y, acc[2].y);
    acc[3].x = fmaf(nrm, f3.x, acc[3].x); acc[3].y = fmaf(nrm, f3.y, acc[3].y);
}

__global__ void __launch_bounds__(256) agg_kernel(const float* __restrict__ bias) {
    int grp  = (blockIdx.x * blockDim.x + threadIdx.x) >> 4;
    int lane = threadIdx.x & 15;
    if (grp >= NN) return;
    const uint4* __restrict__ H = (const uint4*)g_bufA_h;   // 16 uint4 per row
    int s = g_colptr[grp], e = g_colptr[grp + 1];
    float2 acc[4];
    acc[0] = acc[1] = acc[2] = acc[3] = make_float2(0.f, 0.f);
    int i = s;
    for (; i + 4 <= e; i += 4) {
        uint2 e0 = g_edge[i],     e1 = g_edge[i + 1];
        uint2 e2 = g_edge[i + 2], e3 = g_edge[i + 3];
        uint4 v0 = H[e0.x * 16 + lane];
        uint4 v1 = H[e1.x * 16 + lane];
        uint4 v2 = H[e2.x * 16 + lane];
        uint4 v3 = H[e3.x * 16 + lane];
        agg_fma(acc, v0, __uint_as_float(e0.y));
        agg_fma(acc, v1, __uint_as_float(e1.y));
        agg_fma(acc, v2, __uint_as_float(e2.y));
        agg_fma(acc, v3, __uint_as_float(e3.y));
    }
    for (; i < e; i++) {
        uint2 ed = g_edge[i];
        uint4 v = H[ed.x * 16 + lane];
        agg_fma(acc, v, __uint_as_float(ed.y));
    }
    float4 b0 = ((const float4*)bias)[lane * 2];
    float4 b1 = ((const float4*)bias)[lane * 2 + 1];
    float4 o0 = make_float4(fmaxf(acc[0].x + b0.x, 0.f), fmaxf(acc[0].y + b0.y, 0.f),
                            fmaxf(acc[1].x + b0.z, 0.f), fmaxf(acc[1].y + b0.w, 0.f));
    float4 o1 = make_float4(fmaxf(acc[2].x + b1.x, 0.f), fmaxf(acc[2].y + b1.y, 0.f),
                            fmaxf(acc[3].x + b1.z, 0.f), fmaxf(acc[3].y + b1.w, 0.f));
    ((float4*)g_bufB)[grp * 32 + lane * 2]     = o0;
    ((float4*)g_bufB)[grp * 32 + lane * 2 + 1] = o1;
}

// ---------------- pooling + MLP ----------------
__global__ void count_graphs_kernel(const int* __restrict__ batch) {
    int i = blockIdx.x * blockDim.x + threadIdx.x;
    if (i < NN) atomicAdd(&g_gcnt[batch[i]], 1);
}

__global__ void scan_graphs_kernel() {
    __shared__ int s[512];
    if (threadIdx.x < NG) s[threadIdx.x] = g_gcnt[threadIdx.x];
    __syncthreads();
    for (int off = 1; off < NG; off <<= 1) {
        int t = (threadIdx.x >= off && threadIdx.x < NG) ? s[threadIdx.x - off] : 0;
        __syncthreads();
        if (threadIdx.x < NG) s[threadIdx.x] += t;
        __syncthreads();
    }
    if (threadIdx.x < NG) g_gptr[threadIdx.x] = s[threadIdx.x] - g_gcnt[threadIdx.x];
    if (threadIdx.x == NG - 1) g_gptr[NG] = s[NG - 1];
}

__global__ void pool_kernel() {
    int g = blockIdx.x, t = threadIdx.x;   // 128 threads
    int s = g_gptr[g], e = g_gptr[g + 1];
    float acc = 0.f;
    int nidx = s;
    for (; nidx + 4 <= e; nidx += 4) {
        float a0 = g_bufB[(nidx + 0) * 128 + t];
        float a1 = g_bufB[(nidx + 1) * 128 + t];
        float a2 = g_bufB[(nidx + 2) * 128 + t];
        float a3 = g_bufB[(nidx + 3) * 128 + t];
        acc += (a0 + a1) + (a2 + a3);
    }
    for (; nidx < e; nidx++) acc += g_bufB[nidx * 128 + t];
    float c = (float)(e - s);
    g_pool[g * 128 + t] = acc / fmaxf(c, 1.f);
}

__global__ void mlp_kernel(const float* __restrict__ Wm0, const float* __restrict__ bm0,
                           const float* __restrict__ Wm1, const float* __restrict__ bm1,
                           float* __restrict__ out)
{
    __shared__ float rowv[128];
    __shared__ float hid[128];
    int g = blockIdx.x, t = threadIdx.x;
    rowv[t] = g_pool[g * 128 + t];
    __syncthreads();
    float acc = bm0[t];
    #pragma unroll 8
    for (int k = 0; k < 128; k++) acc = fmaf(rowv[k], Wm0[k * 128 + t], acc);
    hid[t] = fmaxf(acc, 0.f) * Wm1[t];
    __syncthreads();
    for (int off = 64; off > 0; off >>= 1) {
        if (t < off) hid[t] += hid[t + off];
        __syncthreads();
    }
    if (t == 0) out[g] = hid[0] + bm1[0];
}

// ---------------- launch ----------------
extern "C" void kernel_launch(void* const* d_in, const int* in_sizes, int n_in,
                              void* d_out, int out_size)
{
    const float* x     = (const float*)d_in[0];
    const int*   ei    = (const int*)d_in[1];     // int32
    // d_in[2] = edge_attr (unused)
    const int*   batch = (const int*)d_in[3];     // int32
    const float* W0  = (const float*)d_in[4];
    const float* b0  = (const float*)d_in[5];
    const float* W1  = (const float*)d_in[6];
    const float* b1  = (const float*)d_in[7];
    const float* W2  = (const float*)d_in[8];
    const float* b2  = (const float*)d_in[9];
    const float* Wm0 = (const float*)d_in[10];
    const float* bm0 = (const float*)d_in[11];
    const float* Wm1 = (const float*)d_in[12];
    const float* bm1 = (const float*)d_in[13];
    float* out = (float*)d_out;

    cudaFuncSetAttribute(gemm_kernel, cudaFuncAttributeMaxDynamicSharedMemorySize, SMEM_GEMM);

    __half* bufA = nullptr;
    float*  bufB = nullptr;
    cudaGetSymbolAddress((void**)&bufA, g_bufA_h);
    cudaGetSymbolAddress((void**)&bufB, g_bufB);

    // preprocessing
    init_kernel<<<391, 256>>>();
    count_edges_kernel<<<3125, 256>>>(ei);
    scan_blocksum_kernel<<<NSCB, 1024>>>();
    scan_part_kernel<<<1, 128>>>();
    scan_local_kernel<<<NSCB, 1024>>>();
    fill_csr_kernel<<<12891, 256>>>(ei);

    // 3 GCN layers
    const float* Wl[3] = {W0, W1, W2};
    const float* bl[3] = {b0, b1, b2};
    const float* in = x;
    for (int l = 0; l < 3; l++) {
        gemm_kernel<<<782, 256, SMEM_GEMM>>>(in, Wl[l], bufA, NN);
        agg_kernel<<<6250, 256>>>(bl[l]);
        in = bufB;
    }

    // pooling + MLP head
    count_graphs_kernel<<<391, 256>>>(batch);
    scan_graphs_kernel<<<1, 512>>>();
    pool_kernel<<<NG, 128>>>();
    mlp_kernel<<<NG, 128>>>(Wm0, bm0, Wm1, bm1, out);
}

// round 16
// speedup vs baseline: 1.3365x; 1.3365x over previous
#include <cuda_runtime.h>
#include <cuda_fp16.h>
#include <mma.h>

using namespace nvcuda;

#define NN 100000
#define NE 3200000
#define HID 128
#define NG  512
#define NSCB 98   // scan blocks: 98*1024 >= NN

// ---------------- static device scratch ----------------
// +128 row pad: wmma A-fragments may read past row n in the last tile.
__device__ __half g_x_h[(NN + 128) * HID];   // fp16 copy of input x (layer-0 GEMM A)
__device__ __half g_bufA_h[NN * HID];        // post-GEMM features (fp16, gather source)
__device__ __half g_bufB_h[(NN + 128) * HID];// post-agg features (fp16; GEMM A / pool src)
__device__ int    g_cnt[NN];                 // in-degree incl. self loop
__device__ int    g_colptr[NN + 1];          // CSR offsets (by target node)
__device__ int    g_cursor[NN];              // fill cursors
__device__ float  g_dis[NN];                 // deg^{-1/2}
__device__ uint2  g_edge[NE + NN];           // packed CSR: (src, norm-bits)
__device__ int    g_part[NSCB];              // scan partials
__device__ int    g_gcnt[NG];                // nodes per graph
__device__ int    g_gptr[NG + 1];            // graph offsets (batch sorted)
__device__ float  g_pool[NG * HID];          // pooled means

// ---------------- preprocessing ----------------
__global__ void init_kernel() {
    int i = blockIdx.x * blockDim.x + threadIdx.x;
    if (i < NN) g_cnt[i] = 1;   // self-loop
    if (i < NG) g_gcnt[i] = 0;
}

// edge_index / batch are int32 (JAX x64-disabled downcasts jnp.int64)
__global__ void count_edges_kernel(const int* __restrict__ ei) {
    int e4 = blockIdx.x * blockDim.x + threadIdx.x;   // NE/4 threads
    if (e4 < NE / 4) {
        int4 c = ((const int4*)(ei + NE))[e4];
        atomicAdd(&g_cnt[c.x], 1);
        atomicAdd(&g_cnt[c.y], 1);
        atomicAdd(&g_cnt[c.z], 1);
        atomicAdd(&g_cnt[c.w], 1);
    }
}

// --- 3-phase exclusive scan of g_cnt -> g_colptr ---
__global__ void scan_blocksum_kernel() {   // 98 blocks x 1024
    __shared__ int wsum[32];
    int t = threadIdx.x, lane = t & 31, wid = t >> 5;
    int i = blockIdx.x * 1024 + t;
    int v = (i < NN) ? g_cnt[i] : 0;
    for (int off = 16; off > 0; off >>= 1) v += __shfl_down_sync(0xffffffffu, v, off);
    if (lane == 0) wsum[wid] = v;
    __syncthreads();
    if (wid == 0) {
        int s = wsum[lane];
        for (int off = 16; off > 0; off >>= 1) s += __shfl_down_sync(0xffffffffu, s, off);
        if (lane == 0) g_part[blockIdx.x] = s;
    }
}

__global__ void scan_part_kernel() {       // 1 block x 128
    __shared__ int s[128];
    int t = threadIdx.x;
    int orig = (t < NSCB) ? g_part[t] : 0;
    s[t] = orig;
    __syncthreads();
    for (int off = 1; off < 128; off <<= 1) {
        int v = (t >= off) ? s[t - off] : 0;
        __syncthreads();
        s[t] += v;
        __syncthreads();
    }
    if (t < NSCB) g_part[t] = s[t] - orig;   // exclusive
    if (t == 127) g_colptr[NN] = s[127];     // total
}

// local scan + colptr/cursor/dis production (fused)
__global__ void scan_local_kernel() {      // 98 blocks x 1024
    __shared__ int wsum[32];
    int t = threadIdx.x, lane = t & 31, wid = t >> 5;
    int i = blockIdx.x * 1024 + t;
    int v = (i < NN) ? g_cnt[i] : 0;
    int x = v;
    for (int off = 1; off < 32; off <<= 1) {
        int y = __shfl_up_sync(0xffffffffu, x, off);
        if (lane >= off) x += y;
    }
    if (lane == 31) wsum[wid] = x;
    __syncthreads();
    if (wid == 0) {
        int y = wsum[lane];
        for (int off = 1; off < 32; off <<= 1) {
            int z = __shfl_up_sync(0xffffffffu, y, off);
            if (lane >= off) y += z;
        }
        wsum[lane] = y;   // inclusive warp sums
    }
    __syncthreads();
    int woff = (wid > 0) ? wsum[wid - 1] : 0;
    if (i < NN) {
        int cp = g_part[blockIdx.x] + woff + x - v;   // exclusive
        g_colptr[i] = cp;
        g_cursor[i] = cp;
        g_dis[i]    = rsqrtf((float)v);               // v >= 1 always
    }
}

__global__ void fill_csr_kernel(const int* __restrict__ ei) {
    int idx = blockIdx.x * blockDim.x + threadIdx.x;
    if (idx < NE) {
        int r = ei[idx];
        int c = ei[NE + idx];
        int p = atomicAdd(&g_cursor[c], 1);
        g_edge[p] = make_uint2((unsigned)r, __float_as_uint(g_dis[r] * g_dis[c]));
    } else if (idx < NE + NN) {
        int i = idx - NE;           // self loop
        int p = atomicAdd(&g_cursor[i], 1);
        float d = g_dis[i];
        g_edge[p] = make_uint2((unsigned)i, __float_as_uint(d * d));
    }
}

// ---------------- x -> fp16 copy (layer-0 GEMM A operand) ----------------
__global__ void convert_x_kernel(const float* __restrict__ X) {
    int idx = blockIdx.x * blockDim.x + threadIdx.x;   // NN*16 uint4 chunks
    if (idx < NN * 16) {
        float4 a = ((const float4*)X)[idx * 2];
        float4 b = ((const float4*)X)[idx * 2 + 1];
        __half2 p0 = __floats2half2_rn(a.x, a.y), p1 = __floats2half2_rn(a.z, a.w);
        __half2 p2 = __floats2half2_rn(b.x, b.y), p3 = __floats2half2_rn(b.z, b.w);
        uint4 o;
        o.x = *(unsigned*)&p0; o.y = *(unsigned*)&p1;
        o.z = *(unsigned*)&p2; o.w = *(unsigned*)&p3;
        ((uint4*)g_x_h)[idx] = o;
    }
}

// ---------------- GEMM (HMMA, split-W, A from global): Yh = half( X @ (Whi+Wlo) ) ----
// W split into fp16 hi+lo removes the systematic W-quantization error.
// A fragments load straight from global fp16 X (L1-resident; each warp touches
// only its own 16 rows). Smem holds only Whi/Wlo; C staging overlaps them after
// a block-wide sync -> 69.6KB/block, 3 blocks/SM.
#define LDH 136                            // fp16 smem leading dim
#define SMEM_GEMM (2 * 128 * LDH * 2)      // 69632 B

__global__ void __launch_bounds__(256) gemm_kernel(
    const __half* __restrict__ X, const float* __restrict__ W,
    __half* __restrict__ Yh, int n)
{
    extern __shared__ char sm[];
    __half* Whi = (__half*)sm;                 // [128][LDH]
    __half* Wlo = (__half*)sm + 128 * LDH;     // [128][LDH]
    float*  Cs  = (float*)sm;                  // [128][128], reused after compute
    int tid = threadIdx.x;
    int warp = tid >> 5, lane = tid & 31;
    int row0 = blockIdx.x * 128;

    // load + hi/lo split W: 128 rows x 16 chunks (8 floats each)
    for (int idx = tid; idx < 128 * 16; idx += 256) {
        int r = idx >> 4, c8 = idx & 15;
        float4 wa = ((const float4*)W)[r * 32 + c8 * 2];
        float4 wb = ((const float4*)W)[r * 32 + c8 * 2 + 1];
        float wf[8] = {wa.x, wa.y, wa.z, wa.w, wb.x, wb.y, wb.z, wb.w};
        __half hh[8], hl[8];
        #pragma unroll
        for (int q = 0; q < 8; q++) {
            __half h = __float2half_rn(wf[q]);
            hh[q] = h;
            hl[q] = __float2half_rn(wf[q] - __half2float(h));
        }
        *(uint4*)&Whi[r * LDH + c8 * 8] = *(uint4*)hh;
        *(uint4*)&Wlo[r * LDH + c8 * 8] = *(uint4*)hl;
    }
    __syncthreads();

    // each warp: 16 rows x 128 cols; acc = X@Whi + X@Wlo (fp32 accum)
    wmma::fragment<wmma::accumulator, 16, 16, 16, float> acc[8];
    #pragma unroll
    for (int j = 0; j < 8; j++) wmma::fill_fragment(acc[j], 0.f);

    const __half* Arow = X + (row0 + warp * 16) * HID;   // padded buffers: safe past n
    #pragma unroll
    for (int k = 0; k < 8; k++) {
        wmma::fragment<wmma::matrix_a, 16, 16, 16, __half, wmma::row_major> a;
        wmma::load_matrix_sync(a, Arow + k * 16, HID);
        #pragma unroll
        for (int j = 0; j < 8; j++) {
            wmma::fragment<wmma::matrix_b, 16, 16, 16, __half, wmma::row_major> bh, bl;
            wmma::load_matrix_sync(bh, &Whi[(k * 16) * LDH + j * 16], LDH);
            wmma::load_matrix_sync(bl, &Wlo[(k * 16) * LDH + j * 16], LDH);
            wmma::mma_sync(acc[j], a, bh, acc[j]);
            wmma::mma_sync(acc[j], a, bl, acc[j]);
        }
    }

    __syncthreads();   // all mma smem reads done before overwriting with C
    #pragma unroll
    for (int j = 0; j < 8; j++)
        wmma::store_matrix_sync(&Cs[(warp * 16) * 128 + j * 16], acc[j], 128, wmma::mem_row_major);
    __syncwarp();

    // pack this warp's 16 rows to fp16 global (2 lanes per row, 8 chunks each)
    int r = warp * 16 + (lane >> 1);
    int gr = row0 + r;
    if (gr < n) {
        int cbase = (lane & 1) * 8;
        #pragma unroll
        for (int j = 0; j < 8; j++) {
            int c8 = cbase + j;
            float4 ca = *(float4*)&Cs[r * 128 + c8 * 8];
            float4 cb = *(float4*)&Cs[r * 128 + c8 * 8 + 4];
            __half2 p0 = __floats2half2_rn(ca.x, ca.y), p1 = __floats2half2_rn(ca.z, ca.w);
            __half2 p2 = __floats2half2_rn(cb.x, cb.y), p3 = __floats2half2_rn(cb.z, cb.w);
            uint4 o;
            o.x = *(unsigned*)&p0; o.y = *(unsigned*)&p1;
            o.z = *(unsigned*)&p2; o.w = *(unsigned*)&p3;
            ((uint4*)Yh)[gr * 16 + c8] = o;
        }
    }
}

// ---------------- aggregation: bufB[v] = relu(bias + sum_e nrm * Hh[src_e]) -> fp16 ----
__device__ __forceinline__ void agg_fma(float2* acc, uint4 v, float nrm) {
    __half2 h0 = *(__half2*)&v.x, h1 = *(__half2*)&v.y;
    __half2 h2 = *(__half2*)&v.z, h3 = *(__half2*)&v.w;
    float2 f0 = __half22float2(h0), f1 = __half22float2(h1);
    float2 f2 = __half22float2(h2), f3 = __half22float2(h3);
    acc[0].x = fmaf(nrm, f0.x, acc[0].x); acc[0].y = fmaf(nrm, f0.y, acc[0].y);
    acc[1].x = fmaf(nrm, f1.x, acc[1].x); acc[1].y = fmaf(nrm, f1.y, acc[1].y);
    acc[2].x = fmaf(nrm, f2.x, acc[2].x); acc[2].y = fmaf(nrm, f2.y, acc[2].y);
    acc[3].x = fmaf(nrm, f3.x, acc[3].x); acc[3].y = fmaf(nrm, f3.y, acc[3].y);
}

__global__ void __launch_bounds__(256) agg_kernel(const float* __restrict__ bias) {
    int grp  = (blockIdx.x * blockDim.x + threadIdx.x) >> 4;
    int lane = threadIdx.x & 15;
    if (grp >= NN) return;
    const uint4* __restrict__ H = (const uint4*)g_bufA_h;   // 16 uint4 per row
    int s = g_colptr[grp], e = g_colptr[grp + 1];
    float2 acc[4];
    acc[0] = acc[1] = acc[2] = acc[3] = make_float2(0.f, 0.f);
    int i = s;
    for (; i + 4 <= e; i += 4) {
        uint2 e0 = g_edge[i],     e1 = g_edge[i + 1];
        uint2 e2 = g_edge[i + 2], e3 = g_edge[i + 3];
        uint4 v0 = H[e0.x * 16 + lane];
        uint4 v1 = H[e1.x * 16 + lane];
        uint4 v2 = H[e2.x * 16 + lane];
        uint4 v3 = H[e3.x * 16 + lane];
        agg_fma(acc, v0, __uint_as_float(e0.y));
        agg_fma(acc, v1, __uint_as_float(e1.y));
        agg_fma(acc, v2, __uint_as_float(e2.y));
        agg_fma(acc, v3, __uint_as_float(e3.y));
    }
    for (; i < e; i++) {
        uint2 ed = g_edge[i];
        uint4 v = H[ed.x * 16 + lane];
        agg_fma(acc, v, __uint_as_float(ed.y));
    }
    float4 b0 = ((const float4*)bias)[lane * 2];
    float4 b1 = ((const float4*)bias)[lane * 2 + 1];
    float o0 = fmaxf(acc[0].x + b0.x, 0.f), o1 = fmaxf(acc[0].y + b0.y, 0.f);
    float o2 = fmaxf(acc[1].x + b0.z, 0.f), o3 = fmaxf(acc[1].y + b0.w, 0.f);
    float o4 = fmaxf(acc[2].x + b1.x, 0.f), o5 = fmaxf(acc[2].y + b1.y, 0.f);
    float o6 = fmaxf(acc[3].x + b1.z, 0.f), o7 = fmaxf(acc[3].y + b1.w, 0.f);
    __half2 p0 = __floats2half2_rn(o0, o1), p1 = __floats2half2_rn(o2, o3);
    __half2 p2 = __floats2half2_rn(o4, o5), p3 = __floats2half2_rn(o6, o7);
    uint4 o;
    o.x = *(unsigned*)&p0; o.y = *(unsigned*)&p1;
    o.z = *(unsigned*)&p2; o.w = *(unsigned*)&p3;
    ((uint4*)g_bufB_h)[grp * 16 + lane] = o;
}

// ---------------- pooling + MLP ----------------
__global__ void count_graphs_kernel(const int* __restrict__ batch) {
    int i = blockIdx.x * blockDim.x + threadIdx.x;
    if (i < NN) atomicAdd(&g_gcnt[batch[i]], 1);
}

__global__ void scan_graphs_kernel() {
    __shared__ int s[512];
    if (threadIdx.x < NG) s[threadIdx.x] = g_gcnt[threadIdx.x];
    __syncthreads();
    for (int off = 1; off < NG; off <<= 1) {
        int t = (threadIdx.x >= off && threadIdx.x < NG) ? s[threadIdx.x - off] : 0;
        __syncthreads();
        if (threadIdx.x < NG) s[threadIdx.x] += t;
        __syncthreads();
    }
    if (threadIdx.x < NG) g_gptr[threadIdx.x] = s[threadIdx.x] - g_gcnt[threadIdx.x];
    if (threadIdx.x == NG - 1) g_gptr[NG] = s[NG - 1];
}

__global__ void pool_kernel() {
    int g = blockIdx.x, t = threadIdx.x;   // 128 threads
    int s = g_gptr[g], e = g_gptr[g + 1];
    float acc = 0.f;
    int nidx = s;
    for (; nidx + 4 <= e; nidx += 4) {
        float a0 = __half2float(g_bufB_h[(nidx + 0) * 128 + t]);
        float a1 = __half2float(g_bufB_h[(nidx + 1) * 128 + t]);
        float a2 = __half2float(g_bufB_h[(nidx + 2) * 128 + t]);
        float a3 = __half2float(g_bufB_h[(nidx + 3) * 128 + t]);
        acc += (a0 + a1) + (a2 + a3);
    }
    for (; nidx < e; nidx++) acc += __half2float(g_bufB_h[nidx * 128 + t]);
    float c = (float)(e - s);
    g_pool[g * 128 + t] = acc / fmaxf(c, 1.f);
}

__global__ void mlp_kernel(const float* __restrict__ Wm0, const float* __restrict__ bm0,
                           const float* __restrict__ Wm1, const float* __restrict__ bm1,
                           float* __restrict__ out)
{
    __shared__ float rowv[128];
    __shared__ float hid[128];
    int g = blockIdx.x, t = threadIdx.x;
    rowv[t] = g_pool[g * 128 + t];
    __syncthreads();
    float acc = bm0[t];
    #pragma unroll 8
    for (int k = 0; k < 128; k++) acc = fmaf(rowv[k], Wm0[k * 128 + t], acc);
    hid[t] = fmaxf(acc, 0.f) * Wm1[t];
    __syncthreads();
    for (int off = 64; off > 0; off >>= 1) {
        if (t < off) hid[t] += hid[t + off];
        __syncthreads();
    }
    if (t == 0) out[g] = hid[0] + bm1[0];
}

// ---------------- launch ----------------
extern "C" void kernel_launch(void* const* d_in, const int* in_sizes, int n_in,
                              void* d_out, int out_size)
{
    const float* x     = (const float*)d_in[0];
    const int*   ei    = (const int*)d_in[1];     // int32
    // d_in[2] = edge_attr (unused)
    const int*   batch = (const int*)d_in[3];     // int32
    const float* W0  = (const float*)d_in[4];
    const float* b0  = (const float*)d_in[5];
    const float* W1  = (const float*)d_in[6];
    const float* b1  = (const float*)d_in[7];
    const float* W2  = (const float*)d_in[8];
    const float* b2  = (const float*)d_in[9];
    const float* Wm0 = (const float*)d_in[10];
    const float* bm0 = (const float*)d_in[11];
    const float* Wm1 = (const float*)d_in[12];
    const float* bm1 = (const float*)d_in[13];
    float* out = (float*)d_out;

    cudaFuncSetAttribute(gemm_kernel, cudaFuncAttributeMaxDynamicSharedMemorySize, SMEM_GEMM);

    __half* xh   = nullptr;
    __half* bufA = nullptr;
    __half* bufB = nullptr;
    cudaGetSymbolAddress((void**)&xh,   g_x_h);
    cudaGetSymbolAddress((void**)&bufA, g_bufA_h);
    cudaGetSymbolAddress((void**)&bufB, g_bufB_h);

    // Side stream + events for preprocessing overlap (host objects only, created
    // once and kept alive: forked streams must outlive graph capture).
    static cudaStream_t s2 = nullptr;
    static cudaEvent_t evFork = nullptr, evCsr = nullptr, evGr = nullptr;
    if (s2 == nullptr) {
        cudaStreamCreateWithFlags(&s2, cudaStreamNonBlocking);
        cudaEventCreateWithFlags(&evFork, cudaEventDisableTiming);
        cudaEventCreateWithFlags(&evCsr,  cudaEventDisableTiming);
        cudaEventCreateWithFlags(&evGr,   cudaEventDisableTiming);
    }

    // fork: side stream builds CSR + graph offsets while main does convert+GEMM0
    cudaEventRecord(evFork, 0);
    cudaStreamWaitEvent(s2, evFork, 0);

    init_kernel<<<391, 256, 0, s2>>>();
    count_edges_kernel<<<3125, 256, 0, s2>>>(ei);
    scan_blocksum_kernel<<<NSCB, 1024, 0, s2>>>();
    scan_part_kernel<<<1, 128, 0, s2>>>();
    scan_local_kernel<<<NSCB, 1024, 0, s2>>>();
    fill_csr_kernel<<<12891, 256, 0, s2>>>(ei);
    cudaEventRecord(evCsr, s2);
    count_graphs_kernel<<<391, 256, 0, s2>>>(batch);
    scan_graphs_kernel<<<1, 512, 0, s2>>>();
    cudaEventRecord(evGr, s2);

    // main stream: layer-0 transform overlapped with CSR build
    convert_x_kernel<<<6250, 256>>>(x);
    gemm_kernel<<<782, 256, SMEM_GEMM>>>(xh, W0, bufA, NN);
    cudaStreamWaitEvent(0, evCsr, 0);   // join: agg needs CSR
    agg_kernel<<<6250, 256>>>(b0);

    gemm_kernel<<<782, 256, SMEM_GEMM>>>(bufB, W1, bufA, NN);
    agg_kernel<<<6250, 256>>>(b1);
    gemm_kernel<<<782, 256, SMEM_GEMM>>>(bufB, W2, bufA, NN);
    agg_kernel<<<6250, 256>>>(b2);

    cudaStreamWaitEvent(0, evGr, 0);    // join: pool needs graph offsets
    pool_kernel<<<NG, 128>>>();
    mlp_kernel<<<NG, 128>>>(Wm0, bm0, Wm1, bm1, out);
}